// round 11
// baseline (speedup 1.0000x reference)
#include <cuda_runtime.h>
#include <cuda_fp16.h>
#include <cstdint>

// Block-diagonal linear: y[n, b*64+j] = sum_{k<64} x[n, b*64+k] * w[b*64+j, b*64+k]
// R11: deep cp.async pipeline. X loaded raw f32 into a 4-buffer smem ring (all 4
// tiles issued up-front); mainloop converts on the fly (LDS.64 + F2FP pack) into
// fp16 m16n8k16 MMA with register-pinned B. Chunk-XOR swizzle -> conflict-free
// on both the cp.async store side and the LDS.64 fragment side.
// Same arithmetic as R10: rel_err ~2.9e-4 (tolerance 1e-3).

#define N_FEAT   4096
#define BLK      64
#define NBLK     64
#define TROWS    64
#define MULTI    4
#define THREADS  256
#define XSP      36                      // u32 stride for W f16 plane (conflict-free)
#define XTILE_B  (TROWS * 256)           // 16384 B per f32 X tile
#define W_OFF    (MULTI * XTILE_B)       // W plane at 64 KB
#define SMEM_B   (W_OFF + BLK * XSP * 4) // 74752 B total

__device__ __forceinline__ uint32_t pack_h2(float a, float b) {
    __half2 H = __float22half2_rn(make_float2(a, b));
    return *(uint32_t*)&H;
}

__device__ __forceinline__ void mma16816(float c[4],
                                         uint32_t a0, uint32_t a1, uint32_t a2, uint32_t a3,
                                         uint32_t b0, uint32_t b1) {
    asm volatile(
        "mma.sync.aligned.m16n8k16.row.col.f32.f16.f16.f32 "
        "{%0,%1,%2,%3}, {%4,%5,%6,%7}, {%8,%9}, {%0,%1,%2,%3};"
        : "+f"(c[0]), "+f"(c[1]), "+f"(c[2]), "+f"(c[3])
        : "r"(a0), "r"(a1), "r"(a2), "r"(a3), "r"(b0), "r"(b1));
}

#define CP_ASYNC16(dst_u32, src_ptr) \
    asm volatile("cp.async.ca.shared.global [%0], [%1], 16;" :: "r"(dst_u32), "l"(src_ptr))
#define CP_COMMIT() asm volatile("cp.async.commit_group;" ::: "memory")
#define CP_WAIT(n)  asm volatile("cp.async.wait_group %0;" :: "n"(n) : "memory")

struct CtaCtx {
    const float* x; float* out;
    uint32_t sx0;            // shared base of X buffers (u32 addr)
    size_t colbase, row0cta;
    int g, tq, m0, nh;
    uint32_t bh[4][4][2];
};

template <int T>
__device__ __forceinline__ void do_tile(const CtaCtx& c) {
    CP_WAIT(MULTI - 1 - T);
    __syncthreads();

    const uint32_t buf = c.sx0 + T * XTILE_B;
    // lane rows r0 = m0+g, r1 = m0+g+8; swizzle key = row & 15 (m0 is mult of 16)
    const uint32_t rb0 = buf + (uint32_t)(c.m0 + c.g) * 256u;
    const uint32_t rb1 = buf + (uint32_t)(c.m0 + c.g + 8) * 256u;
    const uint32_t k0_ = (uint32_t)c.g;          // swizzle key row g
    const uint32_t k1_ = (uint32_t)(c.g + 8) & 15u;

    float acc[4][4];
    #pragma unroll
    for (int i = 0; i < 4; i++)
        #pragma unroll
        for (int j = 0; j < 4; j++) acc[i][j] = 0.f;

    #pragma unroll
    for (int ks = 0; ks < 4; ks++) {
        // f32 col pairs: (16ks+2tq, +1) and (16ks+8+2tq, +1); chunk = col/4
        const uint32_t ch0 = (uint32_t)(4 * ks + (c.tq >> 1));          // delta 0
        const uint32_t ch1 = ch0 + 2u;                                  // delta 8
        const uint32_t ib  = (uint32_t)(c.tq & 1) * 8u;                 // byte in chunk

        float2 f;
        f = *(const float2*)__cvta_shared_to_generic((size_t)(rb0 + ((ch0 ^ k0_) * 16u) + ib));
        uint32_t a0 = pack_h2(f.x, f.y);
        f = *(const float2*)__cvta_shared_to_generic((size_t)(rb1 + ((ch0 ^ k1_) * 16u) + ib));
        uint32_t a1 = pack_h2(f.x, f.y);
        f = *(const float2*)__cvta_shared_to_generic((size_t)(rb0 + ((ch1 ^ k0_) * 16u) + ib));
        uint32_t a2 = pack_h2(f.x, f.y);
        f = *(const float2*)__cvta_shared_to_generic((size_t)(rb1 + ((ch1 ^ k1_) * 16u) + ib));
        uint32_t a3 = pack_h2(f.x, f.y);

        #pragma unroll
        for (int nt = 0; nt < 4; nt++)
            mma16816(acc[nt], a0, a1, a2, a3, c.bh[nt][ks][0], c.bh[nt][ks][1]);
    }

    const size_t row = c.row0cta + (size_t)T * TROWS + c.m0 + c.g;
    #pragma unroll
    for (int nt = 0; nt < 4; nt++) {
        size_t col = c.colbase + (c.nh * 4 + nt) * 8 + c.tq * 2;
        *(float2*)(c.out + row * N_FEAT + col)       = make_float2(acc[nt][0], acc[nt][1]);
        *(float2*)(c.out + (row + 8) * N_FEAT + col) = make_float2(acc[nt][2], acc[nt][3]);
    }
}

__global__ __launch_bounds__(THREADS, 3)
void sl_blockdiag_kernel(const float* __restrict__ x,
                         const float* __restrict__ w,
                         float* __restrict__ out) {
    extern __shared__ __align__(16) char dsm[];
    uint32_t* sW = (uint32_t*)(dsm + W_OFF);

    const int b  = blockIdx.x % NBLK;
    const int tg = blockIdx.x / NBLK;
    const int tid = threadIdx.x;
    const size_t colbase = (size_t)b * BLK;
    const size_t row0cta = (size_t)tg * (TROWS * MULTI);

    const uint32_t sbase = (uint32_t)__cvta_generic_to_shared(dsm);

    // ---- issue cp.async for ALL 4 X tiles (raw f32, chunk-XOR swizzle) ----
    {
        const int r = tid >> 2;            // row 0..63
        const int q = tid & 3;
        const float* srow = x + (row0cta + r) * N_FEAT + colbase;
        const uint32_t drow = sbase + (uint32_t)r * 256u;
        const uint32_t key = (uint32_t)(r & 15);
        #pragma unroll
        for (int p = 0; p < MULTI; p++) {
            const float* s = srow + (size_t)p * TROWS * N_FEAT;
            const uint32_t d = drow + (uint32_t)p * XTILE_B;
            #pragma unroll
            for (int j = 0; j < 4; j++) {
                uint32_t ch = (uint32_t)(4 * j + q);
                CP_ASYNC16(d + ((ch ^ key) * 16u), s + ch * 4);
            }
            CP_COMMIT();
        }
    }

    // ---- stage W_b (fp16 round, packed pairs) while copies fly ----
    #pragma unroll
    for (int i = tid; i < BLK * 16; i += THREADS) {
        int r = i >> 4, q = i & 15;
        float4 v = *(const float4*)(w + (colbase + r) * N_FEAT + colbase + q * 4);
        sW[r * XSP + 2 * q]     = pack_h2(v.x, v.y);
        sW[r * XSP + 2 * q + 1] = pack_h2(v.z, v.w);
    }
    __syncthreads();

    CtaCtx c;
    c.x = x; c.out = out;
    c.sx0 = sbase;
    c.colbase = colbase; c.row0cta = row0cta;

    const int wid  = tid >> 5;
    const int lane = tid & 31;
    c.g  = lane >> 2;
    c.tq = lane & 3;
    const int mg = wid >> 1;
    c.nh = wid & 1;
    c.m0 = mg * 16;

    // ---- B fragments -> registers ----
    #pragma unroll
    for (int nt = 0; nt < 4; nt++) {
        int nrow = (c.nh * 4 + nt) * 8 + c.g;
        #pragma unroll
        for (int ks = 0; ks < 4; ks++) {
            int a = nrow * XSP + ks * 8 + c.tq;
            c.bh[nt][ks][0] = sW[a];
            c.bh[nt][ks][1] = sW[a + 4];
        }
    }

    do_tile<0>(c);
    do_tile<1>(c);
    do_tile<2>(c);
    do_tile<3>(c);
}

extern "C" void kernel_launch(void* const* d_in, const int* in_sizes, int n_in,
                              void* d_out, int out_size) {
    const float* x = (const float*)d_in[0];
    const float* w = (const float*)d_in[1];
    float* out = (float*)d_out;

    const int n_rows = in_sizes[0] / N_FEAT;                 // 8192
    const int tile_groups = n_rows / (TROWS * MULTI);        // 32

    cudaFuncSetAttribute(sl_blockdiag_kernel,
                         cudaFuncAttributeMaxDynamicSharedMemorySize, SMEM_B);

    dim3 grid(NBLK * tile_groups);                           // 2048 CTAs
    sl_blockdiag_kernel<<<grid, THREADS, SMEM_B>>>(x, w, out);
}

// round 14
// speedup vs baseline: 1.2963x; 1.2963x over previous
#include <cuda_runtime.h>
#include <cuda_fp16.h>
#include <cstdint>

// Block-diagonal linear: y[n, b*64+j] = sum_{k<64} x[n, b*64+k] * w[b*64+j, b*64+k]
// R14 (= R12 resubmit; R13 was an infra failure): R10 core (pure fp16 m16n8k16,
// ldmatrix A, reg-pinned B, double-buffered X) + line-minimized global access:
// X staged 2 rows x 256B per warp (4 lines/LDG.128), output staged through smem
// then stored coalesced (4 lines/STG.128, was 8x STG.64 scatter @ 8 lines each).
// rel_err ~2.9e-4 (tolerance 1e-3).

#define N_FEAT   4096
#define BLK      64
#define NBLK     64
#define TROWS    64
#define MULTI    4
#define THREADS  256
#define XSP      36                 // u32 stride X/W planes (ldmatrix conflict-free)
#define PLANE    (TROWS * XSP)      // 2304 u32 per buffer
#define CSP      68                 // f32 stride of C smem tile (LDS.128 conflict-free)

__device__ __forceinline__ uint32_t pack_h2(float a, float b) {
    __half2 H = __float22half2_rn(make_float2(a, b));
    return *(uint32_t*)&H;
}

__device__ __forceinline__ void mma16816(float c[4],
                                         uint32_t a0, uint32_t a1, uint32_t a2, uint32_t a3,
                                         uint32_t b0, uint32_t b1) {
    asm volatile(
        "mma.sync.aligned.m16n8k16.row.col.f32.f16.f16.f32 "
        "{%0,%1,%2,%3}, {%4,%5,%6,%7}, {%8,%9}, {%0,%1,%2,%3};"
        : "+f"(c[0]), "+f"(c[1]), "+f"(c[2]), "+f"(c[3])
        : "r"(a0), "r"(a1), "r"(a2), "r"(a3), "r"(b0), "r"(b1));
}

__device__ __forceinline__ void ldm_x4(uint32_t& r0, uint32_t& r1, uint32_t& r2, uint32_t& r3,
                                       uint32_t addr) {
    asm volatile("ldmatrix.sync.aligned.m8n8.x4.shared.b16 {%0,%1,%2,%3}, [%4];"
                 : "=r"(r0), "=r"(r1), "=r"(r2), "=r"(r3) : "r"(addr));
}

__global__ __launch_bounds__(THREADS, 3)
void sl_blockdiag_kernel(const float* __restrict__ x,
                         const float* __restrict__ w,
                         float* __restrict__ out) {
    __shared__ uint32_t sX[2][PLANE];          // X double buffer (f16x2 packed)
    __shared__ uint32_t sWp[PLANE];            // W plane
    __shared__ float    sC[TROWS * CSP];       // C staging tile (17408 B)

    const int b  = blockIdx.x % NBLK;
    const int tg = blockIdx.x / NBLK;
    const int tid = threadIdx.x;
    const size_t colbase = (size_t)b * BLK;
    const size_t row0cta = (size_t)tg * (TROWS * MULTI);

    // ---- stage W_b once (fp16 round, packed pairs) ----
    #pragma unroll
    for (int i = tid; i < BLK * 16; i += THREADS) {
        int r = i >> 4, q = i & 15;
        float4 v = *(const float4*)(w + (colbase + r) * N_FEAT + colbase + q * 4);
        sWp[r * XSP + 2 * q]     = pack_h2(v.x, v.y);
        sWp[r * XSP + 2 * q + 1] = pack_h2(v.z, v.w);
    }
    __syncthreads();

    const int wid  = tid >> 5;
    const int lane = tid & 31;
    const int g    = lane >> 2;
    const int tq   = lane & 3;
    const int mg   = wid >> 1;
    const int nh   = wid & 1;
    const int m0   = mg * 16;

    // ---- B fragments -> registers (CTA lifetime) ----
    uint32_t bh[4][4][2];
    #pragma unroll
    for (int nt = 0; nt < 4; nt++) {
        int nrow = (nh * 4 + nt) * 8 + g;
        #pragma unroll
        for (int ks = 0; ks < 4; ks++) {
            int a = nrow * XSP + ks * 8 + tq;
            bh[nt][ks][0] = sWp[a];
            bh[nt][ks][1] = sWp[a + 4];
        }
    }

    // ldmatrix address precompute
    const int lane7 = lane & 7;
    const int mat   = lane >> 3;
    const int arow  = m0 + lane7 + ((mat & 1) << 3);
    const int acolu = (mat >> 1) << 2;
    const uint32_t aoff = (uint32_t)(arow * XSP + acolu) * 4u;
    const uint32_t sb0  = (uint32_t)__cvta_generic_to_shared(&sX[0][0]);
    const uint32_t bufbytes = (uint32_t)PLANE * 4u;

    // staging coords: warp = 2 rows x 16 float4-chunks (256B/row -> 4 lines per LDG.128)
    const int xr = tid >> 4;        // base row 0..15
    const int xq = tid & 15;        // float4 chunk within row

    // ---- stage X tile 0 ----
    #pragma unroll
    for (int j = 0; j < 4; j++) {
        int r = xr + 16 * j;
        float4 v = *(const float4*)(x + (row0cta + r) * N_FEAT + colbase + 4 * xq);
        uint32_t* d = &sX[0][r * XSP + 2 * xq];
        d[0] = pack_h2(v.x, v.y);
        d[1] = pack_h2(v.z, v.w);
    }
    __syncthreads();

    for (int t = 0; t < MULTI; t++) {
        // prefetch next tile into registers (same 2-rows-per-warp mapping)
        float4 p[4];
        if (t + 1 < MULTI) {
            const float* base = x + (row0cta + (size_t)(t + 1) * TROWS) * N_FEAT + colbase + 4 * xq;
            #pragma unroll
            for (int j = 0; j < 4; j++)
                p[j] = *(const float4*)(base + (size_t)(xr + 16 * j) * N_FEAT);
        }

        const uint32_t tb = sb0 + (uint32_t)(t & 1) * bufbytes;

        float c[4][4];
        #pragma unroll
        for (int i = 0; i < 4; i++)
            #pragma unroll
            for (int j = 0; j < 4; j++) c[i][j] = 0.f;

        #pragma unroll
        for (int ks = 0; ks < 4; ks++) {
            uint32_t a0, a1, a2, a3;
            ldm_x4(a0, a1, a2, a3, tb + aoff + (uint32_t)(ks * 8) * 4u);
            #pragma unroll
            for (int nt = 0; nt < 4; nt++)
                mma16816(c[nt], a0, a1, a2, a3, bh[nt][ks][0], bh[nt][ks][1]);
        }

        // pack + store next X tile
        if (t + 1 < MULTI) {
            uint32_t* nb = sX[(t + 1) & 1];
            #pragma unroll
            for (int j = 0; j < 4; j++) {
                uint32_t* d = &nb[(xr + 16 * j) * XSP + 2 * xq];
                d[0] = pack_h2(p[j].x, p[j].y);
                d[1] = pack_h2(p[j].z, p[j].w);
            }
        }
        __syncthreads();   // (A) next-X ready; also fences prior tile's C reads

        // ---- epilogue via smem: scatter STS (cheap banks), coalesced STG ----
        {
            const int r0 = m0 + g;
            #pragma unroll
            for (int nt = 0; nt < 4; nt++) {
                int col = nh * 32 + nt * 8 + tq * 2;
                *(float2*)(sC + r0 * CSP + col)       = make_float2(c[nt][0], c[nt][1]);
                *(float2*)(sC + (r0 + 8) * CSP + col) = make_float2(c[nt][2], c[nt][3]);
            }
        }
        __syncthreads();   // (B) C tile complete

        {
            const size_t rowbase = row0cta + (size_t)t * TROWS;
            float* obase = out + rowbase * N_FEAT + colbase + 4 * xq;
            #pragma unroll
            for (int j = 0; j < 4; j++) {
                int r = xr + 16 * j;
                float4 v = *(const float4*)(sC + r * CSP + 4 * xq);
                *(float4*)(obase + (size_t)r * N_FEAT) = v;   // warp: 2 rows x 256B -> 4 lines
            }
        }
    }
}

extern "C" void kernel_launch(void* const* d_in, const int* in_sizes, int n_in,
                              void* d_out, int out_size) {
    const float* x = (const float*)d_in[0];
    const float* w = (const float*)d_in[1];
    float* out = (float*)d_out;

    const int n_rows = in_sizes[0] / N_FEAT;                 // 8192
    const int tile_groups = n_rows / (TROWS * MULTI);        // 32

    dim3 grid(NBLK * tile_groups);                           // 2048 CTAs
    sl_blockdiag_kernel<<<grid, THREADS>>>(x, w, out);
}